// round 4
// baseline (speedup 1.0000x reference)
#include <cuda_runtime.h>
#include <cstdint>

#define N_NODES 20000
#define N_EDGES 320000

typedef unsigned long long u64;

// ---------------- device scratch -----------------------------------------------
__device__ __align__(16) float g_h[N_NODES * 64];              // h = nf@w_up/8
__device__ __align__(16) float g_agg[(size_t)N_NODES * 576];   // m-major planes

// ---------------- helpers -------------------------------------------------------
__device__ __forceinline__ uint32_t f2tf32(float x) {
    uint32_t r; asm("cvt.rna.tf32.f32 %0, %1;" : "=r"(r) : "f"(x)); return r;
}
__device__ __forceinline__ void splitf(float x, uint32_t& hi, uint32_t& lo) {
    hi = f2tf32(x);
    lo = f2tf32(x - __uint_as_float(hi));
}
__device__ __forceinline__ void red4(float* p, float a, float b, float c, float d) {
    asm volatile("red.global.add.v4.f32 [%0], {%1, %2, %3, %4};"
                 :: "l"((u64)__cvta_generic_to_global(p)),
                    "f"(a), "f"(b), "f"(c), "f"(d) : "memory");
}
#define MMA8(C, a0, a1, a2, a3, b0, b1) \
    asm volatile("mma.sync.aligned.m16n8k8.row.col.f32.tf32.tf32.f32 " \
        "{%0,%1,%2,%3}, {%4,%5,%6,%7}, {%8,%9}, {%0,%1,%2,%3};" \
        : "+f"((C)[0]), "+f"((C)[1]), "+f"((C)[2]), "+f"((C)[3]) \
        : "r"(a0), "r"(a1), "r"(a2), "r"(a3), "r"(b0), "r"(b1))

// ---------------- kernel 0: zero agg -------------------------------------------
__global__ void k_zero() {
    size_t i = (size_t)blockIdx.x * 256 + threadIdx.x;
    reinterpret_cast<float4*>(g_agg)[i] = make_float4(0.f, 0.f, 0.f, 0.f);
}

// ---------------- kernel 1: h = nf @ w_up * (1/8) -------------------------------
__global__ void __launch_bounds__(256) k_node_up(const float* __restrict__ nf,
                                                 const float* __restrict__ w) {
    __shared__ __align__(16) float sW[64 * 64];
    __shared__ float sA[32 * 65];
    const int t  = threadIdx.x;
    const int nb = blockIdx.x * 32;
    for (int i = t; i < 4096; i += 256) sW[i] = w[i];
    for (int i = t; i < 2048; i += 256) sA[(i >> 6) * 65 + (i & 63)] = nf[nb * 64 + i];
    __syncthreads();
    const int ty = t >> 4, tx = t & 15;
    const int r0 = ty * 2, c0 = tx * 4;
    float acc[2][4] = {};
#pragma unroll 8
    for (int k = 0; k < 64; k++) {
        float a0 = sA[r0 * 65 + k];
        float a1 = sA[(r0 + 1) * 65 + k];
        float4 b = *reinterpret_cast<const float4*>(&sW[k * 64 + c0]);
        acc[0][0] += a0 * b.x; acc[0][1] += a0 * b.y; acc[0][2] += a0 * b.z; acc[0][3] += a0 * b.w;
        acc[1][0] += a1 * b.x; acc[1][1] += a1 * b.y; acc[1][2] += a1 * b.z; acc[1][3] += a1 * b.w;
    }
#pragma unroll
    for (int i = 0; i < 2; i++)
#pragma unroll
        for (int j = 0; j < 4; j++)
            g_h[(nb + r0 + i) * 64 + c0 + j] = acc[i][j] * 0.125f;
}

// ---------------- fused mma.sync tf32 MLP + message + scatter -------------------
// 256 threads = 8 warps, 128 edges/CTA. Each warp owns 16 edges (one m16 tile):
// fully warp-local -> __syncwarp only. 3xTF32 split for fp32-class accuracy.
// Smem weights padded so bank = (8k + n) % 32 -> conflict-free B-fragment loads.

// K=64 layer: C[8][4] += A(bufIn rows w16..w16+15, cols 0..63) @ W(cols nbase..nbase+63)
__device__ __forceinline__ void mma_layer(const float* __restrict__ bufIn,
                                          const float* __restrict__ sW, int wstride,
                                          int nbase, float C[8][4], int w16, int lane) {
    const int row = lane >> 2, kq = lane & 3, bcol = lane >> 2;
#pragma unroll
    for (int nt = 0; nt < 8; nt++)
        C[nt][0] = C[nt][1] = C[nt][2] = C[nt][3] = 0.f;
#pragma unroll
    for (int kt = 0; kt < 8; kt++) {
        uint32_t ah[4], al[4];
        splitf(bufIn[(w16 + row)     * 72 + kt * 8 + kq],     ah[0], al[0]);
        splitf(bufIn[(w16 + row + 8) * 72 + kt * 8 + kq],     ah[1], al[1]);
        splitf(bufIn[(w16 + row)     * 72 + kt * 8 + 4 + kq], ah[2], al[2]);
        splitf(bufIn[(w16 + row + 8) * 72 + kt * 8 + 4 + kq], ah[3], al[3]);
#pragma unroll
        for (int nt = 0; nt < 8; nt++) {
            const int n = nbase + nt * 8 + bcol;
            uint32_t bh0, bl0, bh1, bl1;
            splitf(sW[(kt * 8 + kq)     * wstride + n], bh0, bl0);
            splitf(sW[(kt * 8 + 4 + kq) * wstride + n], bh1, bl1);
            MMA8(C[nt], ah[0], ah[1], ah[2], ah[3], bh0, bh1);
            MMA8(C[nt], ah[0], ah[1], ah[2], ah[3], bl0, bl1);
            MMA8(C[nt], al[0], al[1], al[2], al[3], bh0, bh1);
        }
    }
}

template <bool DO_SILU>
__device__ __forceinline__ void store_act(float* __restrict__ bufOut, float C[8][4],
                                          float scale, int w16, int lane) {
    const int row = lane >> 2, kq = lane & 3;
#pragma unroll
    for (int nt = 0; nt < 8; nt++) {
        float v0 = C[nt][0] * scale, v1 = C[nt][1] * scale;
        float v2 = C[nt][2] * scale, v3 = C[nt][3] * scale;
        if (DO_SILU) {
            v0 = __fdividef(v0, 1.f + __expf(-v0));
            v1 = __fdividef(v1, 1.f + __expf(-v1));
            v2 = __fdividef(v2, 1.f + __expf(-v2));
            v3 = __fdividef(v3, 1.f + __expf(-v3));
        }
        const int col = nt * 8 + 2 * kq;
        *reinterpret_cast<float2*>(&bufOut[(w16 + row)     * 72 + col]) = make_float2(v0, v1);
        *reinterpret_cast<float2*>(&bufOut[(w16 + row + 8) * 72 + col]) = make_float2(v2, v3);
    }
}

__global__ void __launch_bounds__(256) k_fused(
    const float* __restrict__ radial, const float* __restrict__ vectors,
    const int* __restrict__ senders, const int* __restrict__ receivers,
    const float* __restrict__ w1, const float* __restrict__ w2,
    const float* __restrict__ w3, const float* __restrict__ w4) {
    extern __shared__ float sm[];
    float* sW1  = sm;              //  8 x 72  =   576
    float* sW2  = sm + 576;        // 64 x 72  =  4608
    float* sW3  = sm + 5184;       // 64 x 72  =  4608
    float* sW4  = sm + 9792;       // 64 x 200 = 12800
    float* bufA = sm + 22592;      // 128 x 72 =  9216
    float* bufB = sm + 31808;      // 128 x 72 =  9216  (total 41024 floats = 164096 B)

    const int t    = threadIdx.x;
    const int warp = t >> 5;
    const int lane = t & 31;
    const int w16  = warp * 16;

    for (int i = t; i < 512;   i += 256) sW1[(i >> 6) * 72 + (i & 63)] = w1[i];
    for (int i = t; i < 4096;  i += 256) sW2[(i >> 6) * 72 + (i & 63)] = w2[i];
    for (int i = t; i < 4096;  i += 256) sW3[(i >> 6) * 72 + (i & 63)] = w3[i];
    for (int i = t; i < 12288; i += 256) { int k = i / 192; sW4[k * 200 + (i - k * 192)] = w4[i]; }
    __syncthreads();

    float C[8][4];
    const int row = lane >> 2, kq = lane & 3, bcol = lane >> 2;

    // ---- layer 1: radial[16,8] @ w1[8,64], scale 1/sqrt(8), silu -> bufA ----
    {
        const float* rb = radial + (size_t)(blockIdx.x * 128 + w16) * 8;
        uint32_t ah[4], al[4];
        splitf(rb[row * 8 + kq],             ah[0], al[0]);
        splitf(rb[(row + 8) * 8 + kq],       ah[1], al[1]);
        splitf(rb[row * 8 + 4 + kq],         ah[2], al[2]);
        splitf(rb[(row + 8) * 8 + 4 + kq],   ah[3], al[3]);
#pragma unroll
        for (int nt = 0; nt < 8; nt++) {
            C[nt][0] = C[nt][1] = C[nt][2] = C[nt][3] = 0.f;
            const int n = nt * 8 + bcol;
            uint32_t bh0, bl0, bh1, bl1;
            splitf(sW1[kq * 72 + n],       bh0, bl0);
            splitf(sW1[(4 + kq) * 72 + n], bh1, bl1);
            MMA8(C[nt], ah[0], ah[1], ah[2], ah[3], bh0, bh1);
            MMA8(C[nt], ah[0], ah[1], ah[2], ah[3], bl0, bl1);
            MMA8(C[nt], al[0], al[1], al[2], al[3], bh0, bh1);
        }
        store_act<true>(bufA, C, 0.35355339059327373f, w16, lane);
    }
    __syncwarp();

    // ---- layers 2, 3 ----
    mma_layer(bufA, sW2, 72, 0, C, w16, lane);
    store_act<true>(bufB, C, 0.125f, w16, lane);
    __syncwarp();
    mma_layer(bufB, sW3, 72, 0, C, w16, lane);
    store_act<true>(bufA, C, 0.125f, w16, lane);
    __syncwarp();

    // ---- scatter setup (thread -> edge = w16 + lane/2, half = lane&1) ----
    const int  eloc = w16 + (lane >> 1);
    const int  e    = blockIdx.x * 128 + eloc;
    const int  half = lane & 1;
    const int  snd  = senders[e];
    const int  rcv  = receivers[e];
    const float* hrow = g_h + (size_t)snd * 64 + half * 32;
    float*       aggb = g_agg + (size_t)rcv * 576 + half * 32;

    float Y1[3], Y2[5];
    {
        float vx = vectors[(size_t)e * 3 + 0];
        float vy = vectors[(size_t)e * 3 + 1];
        float vz = vectors[(size_t)e * 3 + 2];
        float rn = rsqrtf(vx * vx + vy * vy + vz * vz);
        float x = vx * rn, y = vy * rn, z = vz * rn;
        const float SQ3 = 1.7320508075688772f, S15 = 3.872983346207417f;
        Y1[0] = SQ3 * x; Y1[1] = SQ3 * y; Y1[2] = SQ3 * z;
        Y2[0] = S15 * x * y; Y2[1] = S15 * y * z;
        Y2[2] = 1.118033988749895f * (3.f * z * z - 1.f);
        Y2[3] = S15 * x * z; Y2[4] = 0.5f * S15 * (x * x - y * y);
    }
    const float SCL = 0.0009765625f;   // 0.125 (w4 norm) * (1/64) * 0.5 (EPS)

    // ---- layer 4: three 64-col segments, each -> bufB -> message + red scatter ----
#pragma unroll
    for (int seg = 0; seg < 3; seg++) {
        mma_layer(bufA, sW4, 200, seg * 64, C, w16, lane);
        store_act<false>(bufB, C, 1.0f, w16, lane);
        __syncwarp();

        const float* drow = bufB + eloc * 72 + half * 32;
        const int NP  = (seg == 0) ? 1 : (seg == 1 ? 3 : 5);
        const int OFF = (seg == 0) ? 0 : (seg == 1 ? 64 : 256);
        const float* Y = (seg == 1) ? Y1 : Y2;
#pragma unroll
        for (int c4 = 0; c4 < 8; c4++) {
            float4 d  = *reinterpret_cast<const float4*>(drow + c4 * 4);
            float4 h4 = *reinterpret_cast<const float4*>(hrow + c4 * 4);
            float u0 = d.x * h4.x * SCL;
            float u1 = d.y * h4.y * SCL;
            float u2 = d.z * h4.z * SCL;
            float u3 = d.w * h4.w * SCL;
            if (seg == 0) {
                red4(aggb + c4 * 4, u0, u1, u2, u3);
            } else {
#pragma unroll
                for (int p = 0; p < 5; p++) {
                    if (p < NP) {
                        float yp = Y[p];
                        red4(aggb + OFF + p * 64 + c4 * 4, u0 * yp, u1 * yp, u2 * yp, u3 * yp);
                    }
                }
            }
        }
        __syncwarp();   // bufB reused next segment
    }
}

// ---------------- kernel 4: down-projection (m-major reads) ---------------------
__global__ void __launch_bounds__(256) k_down(const float* __restrict__ w0,
                                              const float* __restrict__ w1,
                                              const float* __restrict__ w2,
                                              float* __restrict__ out) {
    __shared__ __align__(16) float sW[64 * 64];
    __shared__ float sA[64 * 65];
    const int seg = blockIdx.y;
    const float* W; int roff, woff, stride;
    if (seg == 0)      { W = w0; roff = 0;                   woff = 0;                stride = 1; }
    else if (seg < 4)  { W = w1; roff = 64  + (seg - 1) * 64; woff = 64  + (seg - 1); stride = 3; }
    else               { W = w2; roff = 256 + (seg - 4) * 64; woff = 256 + (seg - 4); stride = 5; }
    const int t  = threadIdx.x;
    const int nb = blockIdx.x * 64;
    for (int i = t; i < 4096; i += 256) sW[i] = W[i];
    for (int i = t; i < 4096; i += 256) {
        int rr = i >> 6, cc = i & 63;
        int n = nb + rr;
        sA[rr * 65 + cc] = (n < N_NODES) ? g_agg[(size_t)n * 576 + roff + cc] : 0.f;
    }
    __syncthreads();
    const int ty = t >> 4, tx = t & 15;
    const int r0 = ty * 4, d0 = tx * 4;
    float acc[4][4] = {};
#pragma unroll 8
    for (int k = 0; k < 64; k++) {
        float a[4];
#pragma unroll
        for (int i = 0; i < 4; i++) a[i] = sA[(r0 + i) * 65 + k];
        float4 b = *reinterpret_cast<const float4*>(&sW[k * 64 + d0]);
#pragma unroll
        for (int i = 0; i < 4; i++) {
            acc[i][0] += a[i] * b.x; acc[i][1] += a[i] * b.y;
            acc[i][2] += a[i] * b.z; acc[i][3] += a[i] * b.w;
        }
    }
#pragma unroll
    for (int i = 0; i < 4; i++) {
        int n = nb + r0 + i;
        if (n < N_NODES) {
#pragma unroll
            for (int j = 0; j < 4; j++)
                out[(size_t)n * 576 + woff + (size_t)(d0 + j) * stride] = acc[i][j] * 0.125f;
        }
    }
}

// ---------------- launcher ------------------------------------------------------
extern "C" void kernel_launch(void* const* d_in, const int* in_sizes, int n_in,
                              void* d_out, int out_size) {
    const float* vectors    = (const float*)d_in[0];
    const float* node_feats = (const float*)d_in[1];
    const float* radial     = (const float*)d_in[2];
    const int*   senders    = (const int*)  d_in[3];
    const int*   receivers  = (const int*)  d_in[4];
    const float* w_up       = (const float*)d_in[5];
    const float* mlp_w1     = (const float*)d_in[6];
    const float* mlp_w2     = (const float*)d_in[7];
    const float* mlp_w3     = (const float*)d_in[8];
    const float* mlp_w4     = (const float*)d_in[9];
    const float* w_down0    = (const float*)d_in[10];
    const float* w_down1    = (const float*)d_in[11];
    const float* w_down2    = (const float*)d_in[12];
    float* out = (float*)d_out;

    const int FUSED_SMEM = 41024 * 4;   // 164096 B
    cudaFuncSetAttribute(k_fused, cudaFuncAttributeMaxDynamicSharedMemorySize, FUSED_SMEM);

    k_zero<<<11250, 256>>>();
    k_node_up<<<625, 256>>>(node_feats, w_up);
    k_fused<<<2500, 256, FUSED_SMEM>>>(radial, vectors, senders, receivers,
                                       mlp_w1, mlp_w2, mlp_w3, mlp_w4);
    k_down<<<dim3(313, 9), 256>>>(w_down0, w_down1, w_down2, out);
}